// round 6
// baseline (speedup 1.0000x reference)
#include <cuda_runtime.h>
#include <cstdint>
#include <math.h>

#define BS_TOTAL 4096
#define DM 1024
#define NSTATE 16
#define RDT 64
#define PDIM 96
#define SEQ 2048
#define NCH 8
#define CLEN 256

// scratch (device globals: no allocation allowed)
__device__ __align__(16) float g_xinT[DM * BS_TOTAL];      // x_in transposed [e][m]
__device__ __align__(16) float g_wT[DM * DM];              // w_in^T [e][k], tf32-rounded
__device__ __align__(16) float g_w2Thi[PDIM * DM];         // (w_in@w_x)^T hi [p][d]
__device__ __align__(16) float g_w2Tlo[PDIM * DM];         // lo residual
__device__ __align__(16) float g_proj[BS_TOTAL * PDIM];    // row-major (dtlow|B|C)
__device__ __align__(16) float g_projP[4 * BS_TOTAL * PDIM];  // k-split partials
__device__ __align__(16) float g_BT[NSTATE * BS_TOTAL];    // B transposed [n][m]
__device__ __align__(16) float g_CT[NSTATE * BS_TOTAL];    // C transposed [n][m]
__device__ __align__(16) float g_dtT[DM * BS_TOTAL];       // dt transposed [d][m]
__device__ __align__(16) float g_inpP[8 * BS_TOTAL * NSTATE];  // G partials
__device__ __align__(16) float g_inpT[NSTATE * BS_TOTAL];  // inp transposed [n][m]
__device__ __align__(16) float g_negA[DM * NSTATE];        // -exp(A_log)
__device__ __align__(16) float g_hc[2 * DM * NSTATE * NCH];   // chunk-final local h
__device__ __align__(16) float g_Pc[2 * DM * NSTATE * NCH];   // chunk decay product
__device__ __align__(16) float g_H0[2 * DM * NSTATE * NCH];   // chunk initial h

__device__ __forceinline__ float round_tf32(float x) {
    uint32_t r;
    asm("cvt.rna.tf32.f32 %0, %1;" : "=r"(r) : "f"(x));
    return __uint_as_float(r);
}

__device__ __forceinline__ void mma_tf32(float* c, const uint32_t* a, const uint32_t* b) {
    asm volatile(
        "mma.sync.aligned.m16n8k8.row.col.f32.tf32.tf32.f32 "
        "{%0,%1,%2,%3}, {%4,%5,%6,%7}, {%8,%9}, {%0,%1,%2,%3};"
        : "+f"(c[0]), "+f"(c[1]), "+f"(c[2]), "+f"(c[3])
        : "r"(a[0]), "r"(a[1]), "r"(a[2]), "r"(a[3]), "r"(b[0]), "r"(b[1]));
}

// ===========================================================================
// Prep: transpose w_in -> g_wT (tf32-rounded); negA; W2 = w_in@w_x split
// ===========================================================================
__global__ void transpose_kernel(const float* __restrict__ W) {
    __shared__ float t[32][33];
    const int x0 = blockIdx.x * 32, y0 = blockIdx.y * 32;
    const int tx = threadIdx.x, ty = threadIdx.y;
#pragma unroll
    for (int i = 0; i < 4; i++)
        t[ty + 8 * i][tx] = W[(size_t)(y0 + ty + 8 * i) * DM + x0 + tx];
    __syncthreads();
#pragma unroll
    for (int i = 0; i < 4; i++)
        g_wT[(size_t)(x0 + ty + 8 * i) * DM + y0 + tx] = round_tf32(t[tx][ty + 8 * i]);
}

__global__ void negA_kernel(const float* __restrict__ A_log) {
    int i = blockIdx.x * 256 + threadIdx.x;
    if (i < DM * NSTATE) g_negA[i] = -__expf(A_log[i]);
}

__global__ __launch_bounds__(256) void w2prep_kernel(const float* __restrict__ Win,
                                                     const float* __restrict__ Wx) {
    __shared__ float wxs[64][96];
    __shared__ float wins[32][64];
    const int tid = threadIdx.x;
    const int d0 = blockIdx.x * 32;
    const int d = tid >> 3, pg = tid & 7;  // p = pg*12 + j
    float acc[12];
#pragma unroll
    for (int j = 0; j < 12; j++) acc[j] = 0.f;

    for (int e0 = 0; e0 < DM; e0 += 64) {
        for (int i = tid; i < 6144; i += 256)
            wxs[i / 96][i % 96] = Wx[(size_t)(e0 + i / 96) * PDIM + (i % 96)];
        for (int i = tid; i < 2048; i += 256)
            wins[i >> 6][i & 63] = Win[(size_t)(d0 + (i >> 6)) * DM + e0 + (i & 63)];
        __syncthreads();
#pragma unroll 4
        for (int e = 0; e < 64; e++) {
            const float wv = wins[d][e];
#pragma unroll
            for (int j = 0; j < 12; j++)
                acc[j] = fmaf(wv, wxs[e][pg * 12 + j], acc[j]);
        }
        __syncthreads();
    }
#pragma unroll
    for (int j = 0; j < 12; j++) {
        const int p = pg * 12 + j;
        const float v = acc[j];
        const float hi = round_tf32(v);
        g_w2Thi[(size_t)p * DM + d0 + d] = hi;
        g_w2Tlo[(size_t)p * DM + d0 + d] = round_tf32(v - hi);
    }
}

// ===========================================================================
// Kernel 1: x_in = x @ w_in via mma.sync tf32, output TRANSPOSED to g_xinT.
// ===========================================================================
#define KC 16
#define KPAD 20

__global__ __launch_bounds__(256) void gemm1_mma_kernel(const float* __restrict__ x) {
    __shared__ float As[2][128][KPAD];
    __shared__ float Bs[2][128][KPAD];
    const int tid = threadIdx.x;
    const int wid = tid >> 5, lid = tid & 31;
    const int gid = lid >> 2, tig = lid & 3;
    const int wm = wid & 3, wn = wid >> 2;
    const int m0 = blockIdx.y * 128, n0 = blockIdx.x * 128;

    const int r0 = tid >> 2, c0 = (tid & 3) * 4;
    const int r1 = (tid + 256) >> 2, c1 = c0;

    float acc[2][8][4];
#pragma unroll
    for (int mi = 0; mi < 2; mi++)
#pragma unroll
        for (int ni = 0; ni < 8; ni++)
#pragma unroll
            for (int q = 0; q < 4; q++) acc[mi][ni][q] = 0.f;

    float4 pa0, pa1, pb0, pb1;
    pa0 = *(const float4*)(x + (size_t)(m0 + r0) * DM + c0);
    pa1 = *(const float4*)(x + (size_t)(m0 + r1) * DM + c1);
    pb0 = *(const float4*)(g_wT + (size_t)(n0 + r0) * DM + c0);
    pb1 = *(const float4*)(g_wT + (size_t)(n0 + r1) * DM + c1);
    {
        float4 v;
        v = pa0; v.x = round_tf32(v.x); v.y = round_tf32(v.y); v.z = round_tf32(v.z); v.w = round_tf32(v.w);
        *(float4*)&As[0][r0][c0] = v;
        v = pa1; v.x = round_tf32(v.x); v.y = round_tf32(v.y); v.z = round_tf32(v.z); v.w = round_tf32(v.w);
        *(float4*)&As[0][r1][c1] = v;
        *(float4*)&Bs[0][r0][c0] = pb0;
        *(float4*)&Bs[0][r1][c1] = pb1;
    }
    __syncthreads();

    const int NK = DM / KC;
    for (int kt = 0; kt < NK; kt++) {
        const int buf = kt & 1;
        if (kt + 1 < NK) {
            const int kb = (kt + 1) * KC;
            pa0 = *(const float4*)(x + (size_t)(m0 + r0) * DM + kb + c0);
            pa1 = *(const float4*)(x + (size_t)(m0 + r1) * DM + kb + c1);
            pb0 = *(const float4*)(g_wT + (size_t)(n0 + r0) * DM + kb + c0);
            pb1 = *(const float4*)(g_wT + (size_t)(n0 + r1) * DM + kb + c1);
        }
#pragma unroll
        for (int ks = 0; ks < 2; ks++) {
            const int kk = ks * 8;
            uint32_t a[2][4], b[8][2];
#pragma unroll
            for (int mi = 0; mi < 2; mi++) {
                const int m = wm * 32 + mi * 16 + gid;
                a[mi][0] = __float_as_uint(As[buf][m][kk + tig]);
                a[mi][1] = __float_as_uint(As[buf][m + 8][kk + tig]);
                a[mi][2] = __float_as_uint(As[buf][m][kk + tig + 4]);
                a[mi][3] = __float_as_uint(As[buf][m + 8][kk + tig + 4]);
            }
#pragma unroll
            for (int ni = 0; ni < 8; ni++) {
                const int n = wn * 64 + ni * 8 + gid;
                b[ni][0] = __float_as_uint(Bs[buf][n][kk + tig]);
                b[ni][1] = __float_as_uint(Bs[buf][n][kk + tig + 4]);
            }
#pragma unroll
            for (int mi = 0; mi < 2; mi++)
#pragma unroll
                for (int ni = 0; ni < 8; ni++)
                    mma_tf32(acc[mi][ni], a[mi], b[ni]);
        }
        if (kt + 1 < NK) {
            const int nb = buf ^ 1;
            float4 v;
            v = pa0; v.x = round_tf32(v.x); v.y = round_tf32(v.y); v.z = round_tf32(v.z); v.w = round_tf32(v.w);
            *(float4*)&As[nb][r0][c0] = v;
            v = pa1; v.x = round_tf32(v.x); v.y = round_tf32(v.y); v.z = round_tf32(v.z); v.w = round_tf32(v.w);
            *(float4*)&As[nb][r1][c1] = v;
            *(float4*)&Bs[nb][r0][c0] = pb0;
            *(float4*)&Bs[nb][r1][c1] = pb1;
        }
        __syncthreads();
    }

    // transposed epilogue: stage 32-col chunks in smem, write g_xinT coalesced.
    float* st = &As[0][0][0];
#pragma unroll
    for (int c = 0; c < 4; c++) {
        if (wn == (c >> 1)) {
            const int nibase = (c & 1) * 4;
#pragma unroll
            for (int mi = 0; mi < 2; mi++)
#pragma unroll
                for (int ni2 = 0; ni2 < 4; ni2++) {
                    const int ni = nibase + ni2;
#pragma unroll
                    for (int q = 0; q < 4; q++) {
                        const int nl = ni2 * 8 + tig * 2 + (q & 1);
                        const int ml = wm * 32 + mi * 16 + gid + ((q >> 1) * 8);
                        st[nl * 132 + ml] = acc[mi][ni][q];
                    }
                }
        }
        __syncthreads();
        {
            const int rl = tid >> 3, mc = (tid & 7) * 16;
            float* dst = g_xinT + (size_t)(n0 + c * 32 + rl) * BS_TOTAL + m0 + mc;
            const float* src = st + rl * 132 + mc;
#pragma unroll
            for (int q = 0; q < 4; q++) *(float4*)(dst + q * 4) = *(const float4*)(src + q * 4);
        }
        __syncthreads();
    }
}

// ===========================================================================
// Kernel 2: proj = x @ W2 via split-tf32 MMA (3 terms). grid (32 m, 4 ksplit).
// CTA 128m x 96p, warps 4m x 2n (32m x 48n each).
// ===========================================================================
__global__ __launch_bounds__(256) void proj_mma_kernel(const float* __restrict__ x) {
    __shared__ float Ah[128][KPAD], Al[128][KPAD];
    __shared__ float Bh[96][KPAD], Bl[96][KPAD];
    const int tid = threadIdx.x;
    const int wid = tid >> 5, lid = tid & 31;
    const int gid = lid >> 2, tig = lid & 3;
    const int wm = wid & 3, wn = wid >> 2;
    const int m0 = blockIdx.x * 128, k0 = blockIdx.y * 256;

    const int ra = tid >> 2, ca = (tid & 3) * 4;  // + row 64
    const int rb = tid >> 2, cb = ca;             // rb<96: tid<384 always; second half tid<128

    float acc[2][6][4];
#pragma unroll
    for (int mi = 0; mi < 2; mi++)
#pragma unroll
        for (int ni = 0; ni < 6; ni++)
#pragma unroll
            for (int q = 0; q < 4; q++) acc[mi][ni][q] = 0.f;

    float4 pa0, pa1, pbh0, pbl0, pbh1, pbl1;
    // chunk 0 loads
    pa0 = *(const float4*)(x + (size_t)(m0 + ra) * DM + k0 + ca);
    pa1 = *(const float4*)(x + (size_t)(m0 + ra + 64) * DM + k0 + ca);
    pbh0 = *(const float4*)(g_w2Thi + (size_t)rb * DM + k0 + cb);
    pbl0 = *(const float4*)(g_w2Tlo + (size_t)rb * DM + k0 + cb);
    if (tid < 128) {
        pbh1 = *(const float4*)(g_w2Thi + (size_t)(rb + 64) * DM + k0 + cb);
        pbl1 = *(const float4*)(g_w2Tlo + (size_t)(rb + 64) * DM + k0 + cb);
    }
    {
        float4 h, l;
        h = pa0;
        h.x = round_tf32(h.x); h.y = round_tf32(h.y); h.z = round_tf32(h.z); h.w = round_tf32(h.w);
        l = make_float4(round_tf32(pa0.x - h.x), round_tf32(pa0.y - h.y),
                        round_tf32(pa0.z - h.z), round_tf32(pa0.w - h.w));
        *(float4*)&Ah[ra][ca] = h; *(float4*)&Al[ra][ca] = l;
        h = pa1;
        h.x = round_tf32(h.x); h.y = round_tf32(h.y); h.z = round_tf32(h.z); h.w = round_tf32(h.w);
        l = make_float4(round_tf32(pa1.x - h.x), round_tf32(pa1.y - h.y),
                        round_tf32(pa1.z - h.z), round_tf32(pa1.w - h.w));
        *(float4*)&Ah[ra + 64][ca] = h; *(float4*)&Al[ra + 64][ca] = l;
        *(float4*)&Bh[rb][cb] = pbh0; *(float4*)&Bl[rb][cb] = pbl0;
        if (tid < 128) { *(float4*)&Bh[rb + 64][cb] = pbh1; *(float4*)&Bl[rb + 64][cb] = pbl1; }
    }
    __syncthreads();

    for (int kt = 0; kt < 16; kt++) {
        if (kt + 1 < 16) {
            const int kb = k0 + (kt + 1) * KC;
            pa0 = *(const float4*)(x + (size_t)(m0 + ra) * DM + kb + ca);
            pa1 = *(const float4*)(x + (size_t)(m0 + ra + 64) * DM + kb + ca);
            pbh0 = *(const float4*)(g_w2Thi + (size_t)rb * DM + kb + cb);
            pbl0 = *(const float4*)(g_w2Tlo + (size_t)rb * DM + kb + cb);
            if (tid < 128) {
                pbh1 = *(const float4*)(g_w2Thi + (size_t)(rb + 64) * DM + kb + cb);
                pbl1 = *(const float4*)(g_w2Tlo + (size_t)(rb + 64) * DM + kb + cb);
            }
        }
#pragma unroll
        for (int ks = 0; ks < 2; ks++) {
            const int kk = ks * 8;
            uint32_t ah[2][4], al[2][4], bh[6][2], bl[6][2];
#pragma unroll
            for (int mi = 0; mi < 2; mi++) {
                const int m = wm * 32 + mi * 16 + gid;
                ah[mi][0] = __float_as_uint(Ah[m][kk + tig]);
                ah[mi][1] = __float_as_uint(Ah[m + 8][kk + tig]);
                ah[mi][2] = __float_as_uint(Ah[m][kk + tig + 4]);
                ah[mi][3] = __float_as_uint(Ah[m + 8][kk + tig + 4]);
                al[mi][0] = __float_as_uint(Al[m][kk + tig]);
                al[mi][1] = __float_as_uint(Al[m + 8][kk + tig]);
                al[mi][2] = __float_as_uint(Al[m][kk + tig + 4]);
                al[mi][3] = __float_as_uint(Al[m + 8][kk + tig + 4]);
            }
#pragma unroll
            for (int ni = 0; ni < 6; ni++) {
                const int n = wn * 48 + ni * 8 + gid;
                bh[ni][0] = __float_as_uint(Bh[n][kk + tig]);
                bh[ni][1] = __float_as_uint(Bh[n][kk + tig + 4]);
                bl[ni][0] = __float_as_uint(Bl[n][kk + tig]);
                bl[ni][1] = __float_as_uint(Bl[n][kk + tig + 4]);
            }
#pragma unroll
            for (int mi = 0; mi < 2; mi++)
#pragma unroll
                for (int ni = 0; ni < 6; ni++) {
                    mma_tf32(acc[mi][ni], ah[mi], bh[ni]);
                    mma_tf32(acc[mi][ni], al[mi], bh[ni]);
                    mma_tf32(acc[mi][ni], ah[mi], bl[ni]);
                }
        }
        __syncthreads();
        if (kt + 1 < 16) {
            float4 h, l;
            h = pa0;
            h.x = round_tf32(h.x); h.y = round_tf32(h.y); h.z = round_tf32(h.z); h.w = round_tf32(h.w);
            l = make_float4(round_tf32(pa0.x - h.x), round_tf32(pa0.y - h.y),
                            round_tf32(pa0.z - h.z), round_tf32(pa0.w - h.w));
            *(float4*)&Ah[ra][ca] = h; *(float4*)&Al[ra][ca] = l;
            h = pa1;
            h.x = round_tf32(h.x); h.y = round_tf32(h.y); h.z = round_tf32(h.z); h.w = round_tf32(h.w);
            l = make_float4(round_tf32(pa1.x - h.x), round_tf32(pa1.y - h.y),
                            round_tf32(pa1.z - h.z), round_tf32(pa1.w - h.w));
            *(float4*)&Ah[ra + 64][ca] = h; *(float4*)&Al[ra + 64][ca] = l;
            *(float4*)&Bh[rb][cb] = pbh0; *(float4*)&Bl[rb][cb] = pbl0;
            if (tid < 128) { *(float4*)&Bh[rb + 64][cb] = pbh1; *(float4*)&Bl[rb + 64][cb] = pbl1; }
        }
        __syncthreads();
    }

    float* base = g_projP + (size_t)blockIdx.y * BS_TOTAL * PDIM;
#pragma unroll
    for (int mi = 0; mi < 2; mi++) {
        const int mrow = m0 + wm * 32 + mi * 16 + gid;
#pragma unroll
        for (int ni = 0; ni < 6; ni++) {
            const int ncol = wn * 48 + ni * 8 + tig * 2;
            *(float2*)(base + (size_t)mrow * PDIM + ncol) =
                make_float2(acc[mi][ni][0], acc[mi][ni][1]);
            *(float2*)(base + (size_t)(mrow + 8) * PDIM + ncol) =
                make_float2(acc[mi][ni][2], acc[mi][ni][3]);
        }
    }
}

// reduce 4 partials -> g_proj row-major; extract B,C transposed
__global__ __launch_bounds__(256) void proj_reduce_kernel() {
    const int idx = blockIdx.x * 256 + threadIdx.x;
    const int m = idx / PDIM, p = idx - m * PDIM;
    float v = 0.f;
#pragma unroll
    for (int ks = 0; ks < 4; ks++)
        v += g_projP[(size_t)ks * BS_TOTAL * PDIM + idx];
    g_proj[idx] = v;
    if (p >= RDT) {
        const int n = p - RDT;
        if (n < NSTATE) g_BT[(size_t)n * BS_TOTAL + m] = v;
        else g_CT[(size_t)(n - NSTATE) * BS_TOTAL + m] = v;
    }
}

// ===========================================================================
// Kernel 3: dt = softplus(dtlow @ w_dt + b)*0.099+0.001, output TRANSPOSED.
// ===========================================================================
__global__ __launch_bounds__(256) void dt_kernel(const float* __restrict__ Wdt,
                                                 const float* __restrict__ bdt) {
    __shared__ float As[64][64];
    __shared__ float Bs[64][68];
    const int tid = threadIdx.x;
    const int m0 = blockIdx.y * 64, d0 = blockIdx.x * 64;
    const int tx = tid & 15, ty = tid >> 4;
    float acc[4][4];
#pragma unroll
    for (int i = 0; i < 4; i++)
#pragma unroll
        for (int j = 0; j < 4; j++) acc[i][j] = 0.f;

    for (int i = tid; i < 1024; i += 256) {
        int r = i >> 4, c4 = (i & 15) * 4;
        *(float4*)&As[r][c4] = *(const float4*)(g_proj + (size_t)(m0 + r) * PDIM + c4);
        *(float4*)&Bs[r][c4] = *(const float4*)(Wdt + (size_t)r * DM + d0 + c4);
    }
    __syncthreads();
#pragma unroll 4
    for (int r = 0; r < 64; r++) {
        float ra[4], rb[4];
#pragma unroll
        for (int i = 0; i < 4; i++) ra[i] = As[ty * 4 + i][r];
        *(float4*)&rb[0] = *(const float4*)&Bs[r][tx * 4];
#pragma unroll
        for (int i = 0; i < 4; i++)
#pragma unroll
            for (int j = 0; j < 4; j++)
                acc[i][j] = fmaf(ra[i], rb[j], acc[i][j]);
    }
#pragma unroll
    for (int i = 0; i < 4; i++)
#pragma unroll
        for (int j = 0; j < 4; j++) {
            float z = acc[i][j] + bdt[d0 + tx * 4 + j];
            float sp = (z > 15.f) ? z : log1pf(__expf(z));
            acc[i][j] = sp * 0.099f + 0.001f;
        }
    __syncthreads();
    float* stg = &Bs[0][0];
#pragma unroll
    for (int j = 0; j < 4; j++)
        *(float4*)&stg[(tx * 4 + j) * 68 + ty * 4] =
            make_float4(acc[0][j], acc[1][j], acc[2][j], acc[3][j]);
    __syncthreads();
    {
        const int dl = tid >> 2, mc = (tid & 3) * 16;
        float* dst = g_dtT + (size_t)(d0 + dl) * BS_TOTAL + m0 + mc;
        const float* src = stg + dl * 68 + mc;
#pragma unroll
        for (int q = 0; q < 4; q++) *(float4*)(dst + q * 4) = *(const float4*)(src + q * 4);
    }
}

// ===========================================================================
// Kernel 4: G partials + reduce -> g_inpT
// ===========================================================================
__global__ __launch_bounds__(256) void inp_part_kernel() {
    __shared__ float nAs[128 * NSTATE];
    const int tid = threadIdx.x;
    const int m0 = blockIdx.x * 256, k0 = blockIdx.y * 128;
    for (int i = tid; i < 128 * NSTATE; i += 256) nAs[i] = g_negA[k0 * NSTATE + i];
    __syncthreads();
    const int m = m0 + tid;
    float acc[NSTATE];
#pragma unroll
    for (int n = 0; n < NSTATE; n++) acc[n] = 0.f;
#pragma unroll 2
    for (int kk = 0; kk < 128; kk++) {
        const float s = g_dtT[(size_t)(k0 + kk) * BS_TOTAL + m] *
                        g_xinT[(size_t)(k0 + kk) * BS_TOTAL + m];
#pragma unroll
        for (int n4 = 0; n4 < 4; n4++) {
            float4 a = *(const float4*)&nAs[kk * NSTATE + n4 * 4];
            acc[n4 * 4 + 0] = fmaf(s, a.x, acc[n4 * 4 + 0]);
            acc[n4 * 4 + 1] = fmaf(s, a.y, acc[n4 * 4 + 1]);
            acc[n4 * 4 + 2] = fmaf(s, a.z, acc[n4 * 4 + 2]);
            acc[n4 * 4 + 3] = fmaf(s, a.w, acc[n4 * 4 + 3]);
        }
    }
    float* o = g_inpP + ((size_t)blockIdx.y * BS_TOTAL + m) * NSTATE;
#pragma unroll
    for (int n4 = 0; n4 < 4; n4++)
        *(float4*)(o + n4 * 4) =
            make_float4(acc[n4 * 4], acc[n4 * 4 + 1], acc[n4 * 4 + 2], acc[n4 * 4 + 3]);
}

__global__ __launch_bounds__(256) void inp_reduce_kernel() {
    const int idx = blockIdx.x * 256 + threadIdx.x;
    const int m = idx >> 4, n = idx & 15;
    float v = 0.f;
#pragma unroll
    for (int ks = 0; ks < 8; ks++)
        v += g_inpP[(size_t)ks * BS_TOTAL * NSTATE + idx];
    g_inpT[(size_t)n * BS_TOTAL + m] = v * g_BT[(size_t)n * BS_TOTAL + m];
}

// ===========================================================================
// Scan pass 1: per-chunk local scan (h from 0) + chunk decay product.
// grid (64 dchunks, 16 = b*8+chunk), block 256 (16 dgroups x 16 lanes).
// ===========================================================================
__global__ __launch_bounds__(256) void scan1_kernel() {
    const int tid = threadIdx.x;
    const int grp = tid >> 4, n = tid & 15;
    const int d = blockIdx.x * 16 + grp;
    const int b = blockIdx.y >> 3, c = blockIdx.y & 7;
    const float A1 = g_negA[d * NSTATE + n];
    const size_t mb = (size_t)b * SEQ + c * CLEN;
    const float* __restrict__ dtp = g_dtT + (size_t)d * BS_TOTAL + mb;
    const float* __restrict__ ip = g_inpT + (size_t)n * BS_TOTAL + mb;

    float h = 0.f, dts = 0.f;
    for (int s0 = 0; s0 < CLEN; s0 += 8) {
        float4 Da = *(const float4*)(dtp + s0), Db = *(const float4*)(dtp + s0 + 4);
        float4 Ia = *(const float4*)(ip + s0), Ib = *(const float4*)(ip + s0 + 4);
        dts += ((Da.x + Da.y) + (Da.z + Da.w)) + ((Db.x + Db.y) + (Db.z + Db.w));
        h = fmaf(__expf(Da.x * A1), h, Ia.x);
        h = fmaf(__expf(Da.y * A1), h, Ia.y);
        h = fmaf(__expf(Da.z * A1), h, Ia.z);
        h = fmaf(__expf(Da.w * A1), h, Ia.w);
        h = fmaf(__expf(Db.x * A1), h, Ib.x);
        h = fmaf(__expf(Db.y * A1), h, Ib.y);
        h = fmaf(__expf(Db.z * A1), h, Ib.z);
        h = fmaf(__expf(Db.w * A1), h, Ib.w);
    }
    const size_t idx = (((size_t)b * DM + d) * NSTATE + n) * NCH + c;
    g_hc[idx] = h;
    g_Pc[idx] = __expf(A1 * dts);
}

// Scan pass 2: 8-step prefix over chunks per channel. 32768 threads.
__global__ __launch_bounds__(256) void scan2_kernel() {
    const size_t t = blockIdx.x * 256 + threadIdx.x;  // (b*DM+d)*16+n
    float H = 0.f;
#pragma unroll
    for (int c = 0; c < NCH; c++) {
        g_H0[t * NCH + c] = H;
        H = fmaf(g_Pc[t * NCH + c], H, g_hc[t * NCH + c]);
    }
}

// Scan pass 3: recompute with correction h_global = h_local + H0 * R.
__global__ __launch_bounds__(256) void scan3_kernel(const float* __restrict__ Dp,
                                                    float* __restrict__ out) {
    __shared__ float sy[2][8][16];
    const int tid = threadIdx.x;
    const int grp = tid >> 4, n = tid & 15;
    const int d0 = blockIdx.x * 16;
    const int d = d0 + grp;
    const int b = blockIdx.y >> 3, c = blockIdx.y & 7;
    const float A1 = g_negA[d * NSTATE + n];
    const float Dpd = Dp[d];
    const float H0 = g_H0[(((size_t)b * DM + d) * NSTATE + n) * NCH + c];
    const size_t mb = (size_t)b * SEQ + c * CLEN;
    const float* __restrict__ dtp = g_dtT + (size_t)d * BS_TOTAL + mb;
    const float* __restrict__ up = g_xinT + (size_t)d * BS_TOTAL + mb;
    const float* __restrict__ ip = g_inpT + (size_t)n * BS_TOTAL + mb;
    const float* __restrict__ cp = g_CT + (size_t)n * BS_TOTAL + mb;
    float* op = out + mb * DM + d0;

    float h = 0.f, R = 1.f;
    for (int s0 = 0; s0 < CLEN; s0 += 8) {
        float4 Da = *(const float4*)(dtp + s0), Db = *(const float4*)(dtp + s0 + 4);
        float4 Ua = *(const float4*)(up + s0), Ub = *(const float4*)(up + s0 + 4);
        float4 Ia = *(const float4*)(ip + s0), Ib = *(const float4*)(ip + s0 + 4);
        float4 Ca = *(const float4*)(cp + s0), Cb = *(const float4*)(cp + s0 + 4);
        float e[8], p[8];
        e[0] = __expf(Da.x * A1); e[1] = __expf(Da.y * A1);
        e[2] = __expf(Da.z * A1); e[3] = __expf(Da.w * A1);
        e[4] = __expf(Db.x * A1); e[5] = __expf(Db.y * A1);
        e[6] = __expf(Db.z * A1); e[7] = __expf(Db.w * A1);
        h = fmaf(e[0], h, Ia.x); R *= e[0]; p[0] = fmaf(H0, R, h) * Ca.x;
        h = fmaf(e[1], h, Ia.y); R *= e[1]; p[1] = fmaf(H0, R, h) * Ca.y;
        h = fmaf(e[2], h, Ia.z); R *= e[2]; p[2] = fmaf(H0, R, h) * Ca.z;
        h = fmaf(e[3], h, Ia.w); R *= e[3]; p[3] = fmaf(H0, R, h) * Ca.w;
        h = fmaf(e[4], h, Ib.x); R *= e[4]; p[4] = fmaf(H0, R, h) * Cb.x;
        h = fmaf(e[5], h, Ib.y); R *= e[5]; p[5] = fmaf(H0, R, h) * Cb.y;
        h = fmaf(e[6], h, Ib.z); R *= e[6]; p[6] = fmaf(H0, R, h) * Cb.z;
        h = fmaf(e[7], h, Ib.w); R *= e[7]; p[7] = fmaf(H0, R, h) * Cb.w;
#pragma unroll
        for (int j = 0; j < 8; j++) {
            p[j] += __shfl_xor_sync(0xffffffffu, p[j], 8);
            p[j] += __shfl_xor_sync(0xffffffffu, p[j], 4);
            p[j] += __shfl_xor_sync(0xffffffffu, p[j], 2);
            p[j] += __shfl_xor_sync(0xffffffffu, p[j], 1);
        }
        const int buf = (s0 >> 3) & 1;
        if (n == 0) {
            sy[buf][0][grp] = fmaf(Dpd, Ua.x, p[0]);
            sy[buf][1][grp] = fmaf(Dpd, Ua.y, p[1]);
            sy[buf][2][grp] = fmaf(Dpd, Ua.z, p[2]);
            sy[buf][3][grp] = fmaf(Dpd, Ua.w, p[3]);
            sy[buf][4][grp] = fmaf(Dpd, Ub.x, p[4]);
            sy[buf][5][grp] = fmaf(Dpd, Ub.y, p[5]);
            sy[buf][6][grp] = fmaf(Dpd, Ub.z, p[6]);
            sy[buf][7][grp] = fmaf(Dpd, Ub.w, p[7]);
        }
        __syncthreads();
        if (tid < 128) {
            const int j = tid >> 4, dd = tid & 15;
            op[(size_t)(s0 + j) * DM + dd] = sy[buf][j][dd];
        }
        __syncthreads();
    }
}

// ===========================================================================
extern "C" void kernel_launch(void* const* d_in, const int* in_sizes, int n_in,
                              void* d_out, int out_size) {
    const float* x     = (const float*)d_in[0];
    const float* w_in  = (const float*)d_in[1];
    const float* w_x   = (const float*)d_in[2];
    const float* w_dt  = (const float*)d_in[3];
    const float* b_dt  = (const float*)d_in[4];
    const float* A_log = (const float*)d_in[5];
    const float* Dp    = (const float*)d_in[6];
    float* out = (float*)d_out;

    transpose_kernel<<<dim3(32, 32), dim3(32, 8)>>>(w_in);
    negA_kernel<<<64, 256>>>(A_log);
    w2prep_kernel<<<32, 256>>>(w_in, w_x);
    gemm1_mma_kernel<<<dim3(DM / 128, BS_TOTAL / 128), 256>>>(x);
    proj_mma_kernel<<<dim3(32, 4), 256>>>(x);
    proj_reduce_kernel<<<(BS_TOTAL * PDIM) / 256, 256>>>();
    dt_kernel<<<dim3(DM / 64, BS_TOTAL / 64), 256>>>(w_dt, b_dt);
    inp_part_kernel<<<dim3(16, 8), 256>>>();
    inp_reduce_kernel<<<(BS_TOTAL * NSTATE) / 256, 256>>>();
    scan1_kernel<<<dim3(64, 16), 256>>>();
    scan2_kernel<<<128, 256>>>();
    scan3_kernel<<<dim3(64, 16), 256>>>(Dp, out);
}

// round 8
// speedup vs baseline: 1.8731x; 1.8731x over previous
#include <cuda_runtime.h>
#include <cstdint>
#include <math.h>

#define BS_TOTAL 4096
#define DM 1024
#define NSTATE 16
#define RDT 64
#define PDIM 96
#define SEQ 2048

// scratch (device globals: no allocation allowed)
__device__ __align__(16) float g_xinT[DM * BS_TOTAL];      // x_in transposed [e][m]
__device__ __align__(16) float g_wT[DM * DM];              // w_in^T [e][k], tf32-rounded
__device__ __align__(16) float g_proj[BS_TOTAL * PDIM];    // row-major (dtlow|B|C)
__device__ __align__(16) float g_projP[16 * BS_TOTAL * PDIM];  // k-split partials
__device__ __align__(16) float g_BT[NSTATE * BS_TOTAL];    // B transposed [n][m]
__device__ __align__(16) float g_CT[NSTATE * BS_TOTAL];    // C transposed [n][m]
__device__ __align__(16) float g_dtT[DM * BS_TOTAL];       // dt transposed [d][m]
__device__ __align__(16) float g_inpP[16 * BS_TOTAL * NSTATE];  // G partials
__device__ __align__(16) float g_inpT[NSTATE * BS_TOTAL];  // inp transposed [n][m]
__device__ __align__(16) float g_negA[DM * NSTATE];        // -exp(A_log)

__device__ __forceinline__ float round_tf32(float x) {
    uint32_t r;
    asm("cvt.rna.tf32.f32 %0, %1;" : "=r"(r) : "f"(x));
    return __uint_as_float(r);
}

__device__ __forceinline__ void mma_tf32(float* c, const uint32_t* a, const uint32_t* b) {
    asm volatile(
        "mma.sync.aligned.m16n8k8.row.col.f32.tf32.tf32.f32 "
        "{%0,%1,%2,%3}, {%4,%5,%6,%7}, {%8,%9}, {%0,%1,%2,%3};"
        : "+f"(c[0]), "+f"(c[1]), "+f"(c[2]), "+f"(c[3])
        : "r"(a[0]), "r"(a[1]), "r"(a[2]), "r"(a[3]), "r"(b[0]), "r"(b[1]));
}

// ===========================================================================
// Prep: transpose w_in -> g_wT (tf32-rounded); negA table
// ===========================================================================
__global__ void transpose_kernel(const float* __restrict__ W) {
    __shared__ float t[32][33];
    const int x0 = blockIdx.x * 32, y0 = blockIdx.y * 32;
    const int tx = threadIdx.x, ty = threadIdx.y;
#pragma unroll
    for (int i = 0; i < 4; i++)
        t[ty + 8 * i][tx] = W[(size_t)(y0 + ty + 8 * i) * DM + x0 + tx];
    __syncthreads();
#pragma unroll
    for (int i = 0; i < 4; i++)
        g_wT[(size_t)(x0 + ty + 8 * i) * DM + y0 + tx] = round_tf32(t[tx][ty + 8 * i]);
}

__global__ void negA_kernel(const float* __restrict__ A_log) {
    int i = blockIdx.x * 256 + threadIdx.x;
    if (i < DM * NSTATE) g_negA[i] = -__expf(A_log[i]);
}

// ===========================================================================
// Kernel 1: x_in = x @ w_in via mma.sync tf32, output TRANSPOSED to g_xinT.
// CTA 128x128, 8 warps (4x2 -> 32x64/warp), K-chunk 16, double-buffered.
// ===========================================================================
#define KC 16
#define KPAD 20

__global__ __launch_bounds__(256) void gemm1_mma_kernel(const float* __restrict__ x) {
    __shared__ float As[2][128][KPAD];
    __shared__ float Bs[2][128][KPAD];
    const int tid = threadIdx.x;
    const int wid = tid >> 5, lid = tid & 31;
    const int gid = lid >> 2, tig = lid & 3;
    const int wm = wid & 3, wn = wid >> 2;
    const int m0 = blockIdx.y * 128, n0 = blockIdx.x * 128;

    const int r0 = tid >> 2, c0 = (tid & 3) * 4;
    const int r1 = (tid + 256) >> 2, c1 = c0;

    float acc[2][8][4];
#pragma unroll
    for (int mi = 0; mi < 2; mi++)
#pragma unroll
        for (int ni = 0; ni < 8; ni++)
#pragma unroll
            for (int q = 0; q < 4; q++) acc[mi][ni][q] = 0.f;

    float4 pa0, pa1, pb0, pb1;
    pa0 = *(const float4*)(x + (size_t)(m0 + r0) * DM + c0);
    pa1 = *(const float4*)(x + (size_t)(m0 + r1) * DM + c1);
    pb0 = *(const float4*)(g_wT + (size_t)(n0 + r0) * DM + c0);
    pb1 = *(const float4*)(g_wT + (size_t)(n0 + r1) * DM + c1);
    {
        float4 v;
        v = pa0; v.x = round_tf32(v.x); v.y = round_tf32(v.y); v.z = round_tf32(v.z); v.w = round_tf32(v.w);
        *(float4*)&As[0][r0][c0] = v;
        v = pa1; v.x = round_tf32(v.x); v.y = round_tf32(v.y); v.z = round_tf32(v.z); v.w = round_tf32(v.w);
        *(float4*)&As[0][r1][c1] = v;
        *(float4*)&Bs[0][r0][c0] = pb0;
        *(float4*)&Bs[0][r1][c1] = pb1;
    }
    __syncthreads();

    const int NK = DM / KC;
    for (int kt = 0; kt < NK; kt++) {
        const int buf = kt & 1;
        if (kt + 1 < NK) {
            const int kb = (kt + 1) * KC;
            pa0 = *(const float4*)(x + (size_t)(m0 + r0) * DM + kb + c0);
            pa1 = *(const float4*)(x + (size_t)(m0 + r1) * DM + kb + c1);
            pb0 = *(const float4*)(g_wT + (size_t)(n0 + r0) * DM + kb + c0);
            pb1 = *(const float4*)(g_wT + (size_t)(n0 + r1) * DM + kb + c1);
        }
#pragma unroll
        for (int ks = 0; ks < 2; ks++) {
            const int kk = ks * 8;
            uint32_t a[2][4], b[8][2];
#pragma unroll
            for (int mi = 0; mi < 2; mi++) {
                const int m = wm * 32 + mi * 16 + gid;
                a[mi][0] = __float_as_uint(As[buf][m][kk + tig]);
                a[mi][1] = __float_as_uint(As[buf][m + 8][kk + tig]);
                a[mi][2] = __float_as_uint(As[buf][m][kk + tig + 4]);
                a[mi][3] = __float_as_uint(As[buf][m + 8][kk + tig + 4]);
            }
#pragma unroll
            for (int ni = 0; ni < 8; ni++) {
                const int n = wn * 64 + ni * 8 + gid;
                b[ni][0] = __float_as_uint(Bs[buf][n][kk + tig]);
                b[ni][1] = __float_as_uint(Bs[buf][n][kk + tig + 4]);
            }
#pragma unroll
            for (int mi = 0; mi < 2; mi++)
#pragma unroll
                for (int ni = 0; ni < 8; ni++)
                    mma_tf32(acc[mi][ni], a[mi], b[ni]);
        }
        if (kt + 1 < NK) {
            const int nb = buf ^ 1;
            float4 v;
            v = pa0; v.x = round_tf32(v.x); v.y = round_tf32(v.y); v.z = round_tf32(v.z); v.w = round_tf32(v.w);
            *(float4*)&As[nb][r0][c0] = v;
            v = pa1; v.x = round_tf32(v.x); v.y = round_tf32(v.y); v.z = round_tf32(v.z); v.w = round_tf32(v.w);
            *(float4*)&As[nb][r1][c1] = v;
            *(float4*)&Bs[nb][r0][c0] = pb0;
            *(float4*)&Bs[nb][r1][c1] = pb1;
        }
        __syncthreads();
    }

    // transposed epilogue: stage 32-col chunks in smem, write g_xinT coalesced.
    float* st = &As[0][0][0];
#pragma unroll
    for (int c = 0; c < 4; c++) {
        if (wn == (c >> 1)) {
            const int nibase = (c & 1) * 4;
#pragma unroll
            for (int mi = 0; mi < 2; mi++)
#pragma unroll
                for (int ni2 = 0; ni2 < 4; ni2++) {
                    const int ni = nibase + ni2;
#pragma unroll
                    for (int q = 0; q < 4; q++) {
                        const int nl = ni2 * 8 + tig * 2 + (q & 1);
                        const int ml = wm * 32 + mi * 16 + gid + ((q >> 1) * 8);
                        st[nl * 132 + ml] = acc[mi][ni][q];
                    }
                }
        }
        __syncthreads();
        {
            const int rl = tid >> 3, mc = (tid & 7) * 16;
            float* dst = g_xinT + (size_t)(n0 + c * 32 + rl) * BS_TOTAL + m0 + mc;
            const float* src = st + rl * 132 + mc;
#pragma unroll
            for (int q = 0; q < 4; q++) *(float4*)(dst + q * 4) = *(const float4*)(src + q * 4);
        }
        __syncthreads();
    }
}

// ===========================================================================
// Kernel 2: proj partials, thin variant. Thread per m, 32 p, k-split 16.
// grid (16 mchunk, 3 pchunk, 16 ksplit) = 768 blocks.
// ===========================================================================
__global__ __launch_bounds__(256) void proj_kernel(const float* __restrict__ Wx) {
    __shared__ float wxs[64 * 32];
    const int tid = threadIdx.x;
    const int m0 = blockIdx.x * 256, p0 = blockIdx.y * 32, k0 = blockIdx.z * 64;

    for (int i = tid; i < 64 * 32; i += 256)
        wxs[i] = Wx[(size_t)(k0 + (i >> 5)) * PDIM + p0 + (i & 31)];
    __syncthreads();

    const int m = m0 + tid;
    float acc[32];
#pragma unroll
    for (int p = 0; p < 32; p++) acc[p] = 0.f;

#pragma unroll 4
    for (int kk = 0; kk < 64; kk++) {
        const float s = g_xinT[(size_t)(k0 + kk) * BS_TOTAL + m];
#pragma unroll
        for (int p4 = 0; p4 < 8; p4++) {
            float4 w = *(const float4*)&wxs[kk * 32 + p4 * 4];
            acc[p4 * 4 + 0] = fmaf(s, w.x, acc[p4 * 4 + 0]);
            acc[p4 * 4 + 1] = fmaf(s, w.y, acc[p4 * 4 + 1]);
            acc[p4 * 4 + 2] = fmaf(s, w.z, acc[p4 * 4 + 2]);
            acc[p4 * 4 + 3] = fmaf(s, w.w, acc[p4 * 4 + 3]);
        }
    }
    float* o = g_projP + ((size_t)blockIdx.z * BS_TOTAL + m) * PDIM + p0;
#pragma unroll
    for (int p4 = 0; p4 < 8; p4++)
        *(float4*)(o + p4 * 4) = make_float4(acc[p4 * 4], acc[p4 * 4 + 1],
                                             acc[p4 * 4 + 2], acc[p4 * 4 + 3]);
}

// reduce 16 partials -> g_proj row-major; extract B,C transposed
__global__ __launch_bounds__(256) void proj_reduce_kernel() {
    const int idx = blockIdx.x * 256 + threadIdx.x;  // 0 .. 4096*96-1
    const int m = idx / PDIM, p = idx - m * PDIM;
    float v = 0.f;
#pragma unroll
    for (int ks = 0; ks < 16; ks++)
        v += g_projP[(size_t)ks * BS_TOTAL * PDIM + idx];
    g_proj[idx] = v;
    if (p >= RDT) {
        const int n = p - RDT;
        if (n < NSTATE) g_BT[(size_t)n * BS_TOTAL + m] = v;
        else g_CT[(size_t)(n - NSTATE) * BS_TOTAL + m] = v;
    }
}

// ===========================================================================
// Kernel 3: dt = softplus(dtlow @ w_dt + b)*0.099+0.001, output TRANSPOSED.
// ===========================================================================
__global__ __launch_bounds__(256) void dt_kernel(const float* __restrict__ Wdt,
                                                 const float* __restrict__ bdt) {
    __shared__ float As[64][64];
    __shared__ float Bs[64][68];
    const int tid = threadIdx.x;
    const int m0 = blockIdx.y * 64, d0 = blockIdx.x * 64;
    const int tx = tid & 15, ty = tid >> 4;
    float acc[4][4];
#pragma unroll
    for (int i = 0; i < 4; i++)
#pragma unroll
        for (int j = 0; j < 4; j++) acc[i][j] = 0.f;

    for (int i = tid; i < 1024; i += 256) {
        int r = i >> 4, c4 = (i & 15) * 4;
        *(float4*)&As[r][c4] = *(const float4*)(g_proj + (size_t)(m0 + r) * PDIM + c4);
        *(float4*)&Bs[r][c4] = *(const float4*)(Wdt + (size_t)r * DM + d0 + c4);
    }
    __syncthreads();
#pragma unroll 4
    for (int r = 0; r < 64; r++) {
        float ra[4], rb[4];
#pragma unroll
        for (int i = 0; i < 4; i++) ra[i] = As[ty * 4 + i][r];
        *(float4*)&rb[0] = *(const float4*)&Bs[r][tx * 4];
#pragma unroll
        for (int i = 0; i < 4; i++)
#pragma unroll
            for (int j = 0; j < 4; j++)
                acc[i][j] = fmaf(ra[i], rb[j], acc[i][j]);
    }
#pragma unroll
    for (int i = 0; i < 4; i++)
#pragma unroll
        for (int j = 0; j < 4; j++) {
            float z = acc[i][j] + bdt[d0 + tx * 4 + j];
            float sp = (z > 15.f) ? z : log1pf(__expf(z));
            acc[i][j] = sp * 0.099f + 0.001f;
        }
    __syncthreads();
    float* stg = &Bs[0][0];
#pragma unroll
    for (int j = 0; j < 4; j++)
        *(float4*)&stg[(tx * 4 + j) * 68 + ty * 4] =
            make_float4(acc[0][j], acc[1][j], acc[2][j], acc[3][j]);
    __syncthreads();
    {
        const int dl = tid >> 2, mc = (tid & 3) * 16;
        float* dst = g_dtT + (size_t)(d0 + dl) * BS_TOTAL + m0 + mc;
        const float* src = stg + dl * 68 + mc;
#pragma unroll
        for (int q = 0; q < 4; q++) *(float4*)(dst + q * 4) = *(const float4*)(src + q * 4);
    }
}

// ===========================================================================
// Kernel 4: G partials: grid (16 mchunk, 16 ksplit) = 256 blocks.
// ===========================================================================
__global__ __launch_bounds__(256) void inp_part_kernel() {
    __shared__ float nAs[64 * NSTATE];
    const int tid = threadIdx.x;
    const int m0 = blockIdx.x * 256, k0 = blockIdx.y * 64;
    for (int i = tid; i < 64 * NSTATE; i += 256) nAs[i] = g_negA[k0 * NSTATE + i];
    __syncthreads();
    const int m = m0 + tid;
    float acc[NSTATE];
#pragma unroll
    for (int n = 0; n < NSTATE; n++) acc[n] = 0.f;
#pragma unroll 2
    for (int kk = 0; kk < 64; kk++) {
        const float s = g_dtT[(size_t)(k0 + kk) * BS_TOTAL + m] *
                        g_xinT[(size_t)(k0 + kk) * BS_TOTAL + m];
#pragma unroll
        for (int n4 = 0; n4 < 4; n4++) {
            float4 a = *(const float4*)&nAs[kk * NSTATE + n4 * 4];
            acc[n4 * 4 + 0] = fmaf(s, a.x, acc[n4 * 4 + 0]);
            acc[n4 * 4 + 1] = fmaf(s, a.y, acc[n4 * 4 + 1]);
            acc[n4 * 4 + 2] = fmaf(s, a.z, acc[n4 * 4 + 2]);
            acc[n4 * 4 + 3] = fmaf(s, a.w, acc[n4 * 4 + 3]);
        }
    }
    float* o = g_inpP + ((size_t)blockIdx.y * BS_TOTAL + m) * NSTATE;
#pragma unroll
    for (int n4 = 0; n4 < 4; n4++)
        *(float4*)(o + n4 * 4) =
            make_float4(acc[n4 * 4], acc[n4 * 4 + 1], acc[n4 * 4 + 2], acc[n4 * 4 + 3]);
}

__global__ __launch_bounds__(256) void inp_reduce_kernel() {
    const int idx = blockIdx.x * 256 + threadIdx.x;
    const int m = idx >> 4, n = idx & 15;
    float v = 0.f;
#pragma unroll
    for (int ks = 0; ks < 16; ks++)
        v += g_inpP[(size_t)ks * BS_TOTAL * NSTATE + idx];
    g_inpT[(size_t)n * BS_TOTAL + m] = v * g_BT[(size_t)n * BS_TOTAL + m];
}

// ===========================================================================
// Kernel 5: scan. Block = 16 groups (16 consecutive d), group = 16 lanes (n).
// All streams time-contiguous; outputs staged in smem for coalesced stores.
// ===========================================================================
__global__ __launch_bounds__(256) void scan_kernel(const float* __restrict__ Dp,
                                                   float* __restrict__ out) {
    __shared__ float sy[2][8][16];
    const int tid = threadIdx.x;
    const int grp = tid >> 4, n = tid & 15;
    const int d0 = blockIdx.x * 16, b = blockIdx.y;
    const int d = d0 + grp;
    const float A1 = g_negA[d * NSTATE + n];
    const float Dpd = Dp[d];
    const size_t mb = (size_t)b * SEQ;
    const float* __restrict__ dtp = g_dtT + (size_t)d * BS_TOTAL + mb;
    const float* __restrict__ up = g_xinT + (size_t)d * BS_TOTAL + mb;
    const float* __restrict__ ip = g_inpT + (size_t)n * BS_TOTAL + mb;
    const float* __restrict__ cp = g_CT + (size_t)n * BS_TOTAL + mb;
    float* op = out + mb * DM + d0;

    float4 Da, Db, Ua, Ub, Ia, Ib, Ca, Cb;
    Da = *(const float4*)(dtp); Db = *(const float4*)(dtp + 4);
    Ua = *(const float4*)(up);  Ub = *(const float4*)(up + 4);
    Ia = *(const float4*)(ip);  Ib = *(const float4*)(ip + 4);
    Ca = *(const float4*)(cp);  Cb = *(const float4*)(cp + 4);

    float h = 0.f;
    for (int s0 = 0; s0 < SEQ; s0 += 8) {
        float4 nDa, nDb, nUa, nUb, nIa, nIb, nCa, nCb;
        if (s0 + 8 < SEQ) {
            nDa = *(const float4*)(dtp + s0 + 8); nDb = *(const float4*)(dtp + s0 + 12);
            nUa = *(const float4*)(up + s0 + 8);  nUb = *(const float4*)(up + s0 + 12);
            nIa = *(const float4*)(ip + s0 + 8);  nIb = *(const float4*)(ip + s0 + 12);
            nCa = *(const float4*)(cp + s0 + 8);  nCb = *(const float4*)(cp + s0 + 12);
        }
        float e[8], p[8];
        e[0] = __expf(Da.x * A1); e[1] = __expf(Da.y * A1);
        e[2] = __expf(Da.z * A1); e[3] = __expf(Da.w * A1);
        e[4] = __expf(Db.x * A1); e[5] = __expf(Db.y * A1);
        e[6] = __expf(Db.z * A1); e[7] = __expf(Db.w * A1);
        h = fmaf(e[0], h, Ia.x); p[0] = h * Ca.x;
        h = fmaf(e[1], h, Ia.y); p[1] = h * Ca.y;
        h = fmaf(e[2], h, Ia.z); p[2] = h * Ca.z;
        h = fmaf(e[3], h, Ia.w); p[3] = h * Ca.w;
        h = fmaf(e[4], h, Ib.x); p[4] = h * Cb.x;
        h = fmaf(e[5], h, Ib.y); p[5] = h * Cb.y;
        h = fmaf(e[6], h, Ib.z); p[6] = h * Cb.z;
        h = fmaf(e[7], h, Ib.w); p[7] = h * Cb.w;
#pragma unroll
        for (int j = 0; j < 8; j++) {
            p[j] += __shfl_xor_sync(0xffffffffu, p[j], 8);
            p[j] += __shfl_xor_sync(0xffffffffu, p[j], 4);
            p[j] += __shfl_xor_sync(0xffffffffu, p[j], 2);
            p[j] += __shfl_xor_sync(0xffffffffu, p[j], 1);
        }
        const int buf = (s0 >> 3) & 1;
        if (n == 0) {
            sy[buf][0][grp] = fmaf(Dpd, Ua.x, p[0]);
            sy[buf][1][grp] = fmaf(Dpd, Ua.y, p[1]);
            sy[buf][2][grp] = fmaf(Dpd, Ua.z, p[2]);
            sy[buf][3][grp] = fmaf(Dpd, Ua.w, p[3]);
            sy[buf][4][grp] = fmaf(Dpd, Ub.x, p[4]);
            sy[buf][5][grp] = fmaf(Dpd, Ub.y, p[5]);
            sy[buf][6][grp] = fmaf(Dpd, Ub.z, p[6]);
            sy[buf][7][grp] = fmaf(Dpd, Ub.w, p[7]);
        }
        __syncthreads();
        if (tid < 128) {
            const int j = tid >> 4, dd = tid & 15;
            op[(size_t)(s0 + j) * DM + dd] = sy[buf][j][dd];
        }
        Da = nDa; Db = nDb; Ua = nUa; Ub = nUb;
        Ia = nIa; Ib = nIb; Ca = nCa; Cb = nCb;
    }
}

// ===========================================================================
extern "C" void kernel_launch(void* const* d_in, const int* in_sizes, int n_in,
                              void* d_out, int out_size) {
    const float* x     = (const float*)d_in[0];
    const float* w_in  = (const float*)d_in[1];
    const float* w_x   = (const float*)d_in[2];
    const float* w_dt  = (const float*)d_in[3];
    const float* b_dt  = (const float*)d_in[4];
    const float* A_log = (const float*)d_in[5];
    const float* Dp    = (const float*)d_in[6];
    float* out = (float*)d_out;

    transpose_kernel<<<dim3(32, 32), dim3(32, 8)>>>(w_in);
    negA_kernel<<<64, 256>>>(A_log);
    gemm1_mma_kernel<<<dim3(DM / 128, BS_TOTAL / 128), 256>>>(x);
    proj_kernel<<<dim3(16, 3, 16), 256>>>(w_x);
    proj_reduce_kernel<<<(BS_TOTAL * PDIM) / 256, 256>>>();
    dt_kernel<<<dim3(DM / 64, BS_TOTAL / 64), 256>>>(w_dt, b_dt);
    inp_part_kernel<<<dim3(16, 16), 256>>>();
    inp_reduce_kernel<<<(BS_TOTAL * NSTATE) / 256, 256>>>();
    scan_kernel<<<dim3(64, 2), 256>>>(Dp, out);
}

// round 9
// speedup vs baseline: 1.8987x; 1.0136x over previous
#include <cuda_runtime.h>
#include <cstdint>
#include <math.h>

#define BS_TOTAL 4096
#define DM 1024
#define NSTATE 16
#define RDT 64
#define PDIM 96
#define SEQ 2048

// scratch (device globals: no allocation allowed)
__device__ __align__(16) float g_xinT[DM * BS_TOTAL];      // x_in transposed [e][m]
__device__ __align__(16) float g_wT[DM * DM];              // w_in^T [e][k], tf32-rounded
__device__ __align__(16) float g_proj[BS_TOTAL * PDIM];    // row-major (dtlow|B|C)
__device__ __align__(16) float g_projP[16 * BS_TOTAL * PDIM];  // k-split partials
__device__ __align__(16) float g_BT[NSTATE * BS_TOTAL];    // B transposed [n][m]
__device__ __align__(16) float g_CT[NSTATE * BS_TOTAL];    // C transposed [n][m]
__device__ __align__(16) float g_dtT[DM * BS_TOTAL];       // dt transposed [d][m]
__device__ __align__(16) float g_inpP[16 * BS_TOTAL * NSTATE];  // G partials
__device__ __align__(16) float g_inpT[NSTATE * BS_TOTAL];  // inp transposed [n][m]
__device__ __align__(16) float g_negA[DM * NSTATE];        // -exp(A_log)

__device__ __forceinline__ float round_tf32(float x) {
    uint32_t r;
    asm("cvt.rna.tf32.f32 %0, %1;" : "=r"(r) : "f"(x));
    return __uint_as_float(r);
}

__device__ __forceinline__ void mma_tf32(float* c, const uint32_t* a, const uint32_t* b) {
    asm volatile(
        "mma.sync.aligned.m16n8k8.row.col.f32.tf32.tf32.f32 "
        "{%0,%1,%2,%3}, {%4,%5,%6,%7}, {%8,%9}, {%0,%1,%2,%3};"
        : "+f"(c[0]), "+f"(c[1]), "+f"(c[2]), "+f"(c[3])
        : "r"(a[0]), "r"(a[1]), "r"(a[2]), "r"(a[3]), "r"(b[0]), "r"(b[1]));
}

// ===========================================================================
// Prep: transpose w_in -> g_wT (tf32-rounded); negA table
// ===========================================================================
__global__ void transpose_kernel(const float* __restrict__ W) {
    __shared__ float t[32][33];
    const int x0 = blockIdx.x * 32, y0 = blockIdx.y * 32;
    const int tx = threadIdx.x, ty = threadIdx.y;
#pragma unroll
    for (int i = 0; i < 4; i++)
        t[ty + 8 * i][tx] = W[(size_t)(y0 + ty + 8 * i) * DM + x0 + tx];
    __syncthreads();
#pragma unroll
    for (int i = 0; i < 4; i++)
        g_wT[(size_t)(x0 + ty + 8 * i) * DM + y0 + tx] = round_tf32(t[tx][ty + 8 * i]);
}

__global__ void negA_kernel(const float* __restrict__ A_log) {
    int i = blockIdx.x * 256 + threadIdx.x;
    if (i < DM * NSTATE) g_negA[i] = -__expf(A_log[i]);
}

// ===========================================================================
// Kernel 1: x_in = x @ w_in via mma.sync tf32, output TRANSPOSED to g_xinT.
// CTA 128x128, 4 warps (2x2 -> 64x64/warp), K-chunk 8, double-buffered.
// Smem fragment traffic 33% lower than the 8-warp/32x64 config.
// ===========================================================================
#define KC 8
#define KPAD 12
#define ABUF 1536  // 128 * KPAD

__global__ __launch_bounds__(128) void gemm1_mma_kernel(const float* __restrict__ x) {
    __shared__ float sm[4 * ABUF];  // As[2] | Bs[2]; reused as 32x132 stage
    const int tid = threadIdx.x;
    const int wid = tid >> 5, lid = tid & 31;
    const int gid = lid >> 2, tig = lid & 3;
    const int wm = wid & 1, wn = wid >> 1;
    const int m0 = blockIdx.y * 128, n0 = blockIdx.x * 128;

    const int r0 = tid >> 1, c0 = (tid & 1) * 4;  // rows r0, r0+64

    float acc[4][8][4];
#pragma unroll
    for (int mi = 0; mi < 4; mi++)
#pragma unroll
        for (int ni = 0; ni < 8; ni++)
#pragma unroll
            for (int q = 0; q < 4; q++) acc[mi][ni][q] = 0.f;

#define AS_(b, m, k) sm[(b) * ABUF + (m) * KPAD + (k)]
#define BSS(b, n, k) sm[2 * ABUF + (b) * ABUF + (n) * KPAD + (k)]

    float4 pa0, pa1, pb0, pb1;
    pa0 = *(const float4*)(x + (size_t)(m0 + r0) * DM + c0);
    pa1 = *(const float4*)(x + (size_t)(m0 + r0 + 64) * DM + c0);
    pb0 = *(const float4*)(g_wT + (size_t)(n0 + r0) * DM + c0);
    pb1 = *(const float4*)(g_wT + (size_t)(n0 + r0 + 64) * DM + c0);
    {
        float4 v;
        v = pa0; v.x = round_tf32(v.x); v.y = round_tf32(v.y); v.z = round_tf32(v.z); v.w = round_tf32(v.w);
        *(float4*)&AS_(0, r0, c0) = v;
        v = pa1; v.x = round_tf32(v.x); v.y = round_tf32(v.y); v.z = round_tf32(v.z); v.w = round_tf32(v.w);
        *(float4*)&AS_(0, r0 + 64, c0) = v;
        *(float4*)&BSS(0, r0, c0) = pb0;
        *(float4*)&BSS(0, r0 + 64, c0) = pb1;
    }
    __syncthreads();

    const int NK = DM / KC;  // 128
    for (int kt = 0; kt < NK; kt++) {
        const int buf = kt & 1;
        if (kt + 1 < NK) {
            const int kb = (kt + 1) * KC;
            pa0 = *(const float4*)(x + (size_t)(m0 + r0) * DM + kb + c0);
            pa1 = *(const float4*)(x + (size_t)(m0 + r0 + 64) * DM + kb + c0);
            pb0 = *(const float4*)(g_wT + (size_t)(n0 + r0) * DM + kb + c0);
            pb1 = *(const float4*)(g_wT + (size_t)(n0 + r0 + 64) * DM + kb + c0);
        }
        {
            uint32_t a[4][4], b[8][2];
#pragma unroll
            for (int mi = 0; mi < 4; mi++) {
                const int m = wm * 64 + mi * 16 + gid;
                a[mi][0] = __float_as_uint(AS_(buf, m, tig));
                a[mi][1] = __float_as_uint(AS_(buf, m + 8, tig));
                a[mi][2] = __float_as_uint(AS_(buf, m, tig + 4));
                a[mi][3] = __float_as_uint(AS_(buf, m + 8, tig + 4));
            }
#pragma unroll
            for (int ni = 0; ni < 8; ni++) {
                const int n = wn * 64 + ni * 8 + gid;
                b[ni][0] = __float_as_uint(BSS(buf, n, tig));
                b[ni][1] = __float_as_uint(BSS(buf, n, tig + 4));
            }
#pragma unroll
            for (int mi = 0; mi < 4; mi++)
#pragma unroll
                for (int ni = 0; ni < 8; ni++)
                    mma_tf32(acc[mi][ni], a[mi], b[ni]);
        }
        if (kt + 1 < NK) {
            const int nb = buf ^ 1;
            float4 v;
            v = pa0; v.x = round_tf32(v.x); v.y = round_tf32(v.y); v.z = round_tf32(v.z); v.w = round_tf32(v.w);
            *(float4*)&AS_(nb, r0, c0) = v;
            v = pa1; v.x = round_tf32(v.x); v.y = round_tf32(v.y); v.z = round_tf32(v.z); v.w = round_tf32(v.w);
            *(float4*)&AS_(nb, r0 + 64, c0) = v;
            *(float4*)&BSS(nb, r0, c0) = pb0;
            *(float4*)&BSS(nb, r0 + 64, c0) = pb1;
        }
        __syncthreads();
    }

    // transposed epilogue: stage 32-n x 128-m chunks in smem, write coalesced.
#pragma unroll
    for (int c = 0; c < 4; c++) {
        if (wn == (c >> 1)) {
            const int nibase = (c & 1) * 4;
#pragma unroll
            for (int mi = 0; mi < 4; mi++)
#pragma unroll
                for (int ni2 = 0; ni2 < 4; ni2++) {
                    const int ni = nibase + ni2;
#pragma unroll
                    for (int q = 0; q < 4; q++) {
                        const int nl = ni2 * 8 + tig * 2 + (q & 1);
                        const int ml = wm * 64 + mi * 16 + gid + ((q >> 1) * 8);
                        sm[nl * 132 + ml] = acc[mi][ni][q];
                    }
                }
        }
        __syncthreads();
        {
            const int rl = tid >> 2, mc = (tid & 3) * 32;
            float* dst = g_xinT + (size_t)(n0 + c * 32 + rl) * BS_TOTAL + m0 + mc;
            const float* src = sm + rl * 132 + mc;
#pragma unroll
            for (int q = 0; q < 8; q++) *(float4*)(dst + q * 4) = *(const float4*)(src + q * 4);
        }
        __syncthreads();
    }
}

// ===========================================================================
// Kernel 2: proj partials. Thread per 4m (float4), 8 p, k-split 16.
// grid (4 mchunk, 12 pchunk, 16 ksplit) = 768 blocks. FMA-bound per design.
// ===========================================================================
__global__ __launch_bounds__(256) void proj_kernel(const float* __restrict__ Wx) {
    __shared__ float wxs[64 * 8];
    const int tid = threadIdx.x;
    const int m0 = blockIdx.x * 1024, p0 = blockIdx.y * 8, k0 = blockIdx.z * 64;

    for (int i = tid; i < 64 * 8; i += 256)
        wxs[i] = Wx[(size_t)(k0 + (i >> 3)) * PDIM + p0 + (i & 7)];
    __syncthreads();

    const int m = m0 + tid * 4;
    float acc[4][8];
#pragma unroll
    for (int i = 0; i < 4; i++)
#pragma unroll
        for (int p = 0; p < 8; p++) acc[i][p] = 0.f;

#pragma unroll 4
    for (int kk = 0; kk < 64; kk++) {
        float4 s = *(const float4*)(g_xinT + (size_t)(k0 + kk) * BS_TOTAL + m);
#pragma unroll
        for (int p = 0; p < 8; p++) {
            const float w = wxs[kk * 8 + p];
            acc[0][p] = fmaf(s.x, w, acc[0][p]);
            acc[1][p] = fmaf(s.y, w, acc[1][p]);
            acc[2][p] = fmaf(s.z, w, acc[2][p]);
            acc[3][p] = fmaf(s.w, w, acc[3][p]);
        }
    }
    float* o = g_projP + ((size_t)blockIdx.z * BS_TOTAL + m) * PDIM + p0;
#pragma unroll
    for (int i = 0; i < 4; i++) {
        *(float4*)(o + (size_t)i * PDIM) =
            make_float4(acc[i][0], acc[i][1], acc[i][2], acc[i][3]);
        *(float4*)(o + (size_t)i * PDIM + 4) =
            make_float4(acc[i][4], acc[i][5], acc[i][6], acc[i][7]);
    }
}

// reduce 16 partials -> g_proj row-major; extract B,C transposed
__global__ __launch_bounds__(256) void proj_reduce_kernel() {
    const int idx = blockIdx.x * 256 + threadIdx.x;
    const int m = idx / PDIM, p = idx - m * PDIM;
    float v = 0.f;
#pragma unroll
    for (int ks = 0; ks < 16; ks++)
        v += g_projP[(size_t)ks * BS_TOTAL * PDIM + idx];
    g_proj[idx] = v;
    if (p >= RDT) {
        const int n = p - RDT;
        if (n < NSTATE) g_BT[(size_t)n * BS_TOTAL + m] = v;
        else g_CT[(size_t)(n - NSTATE) * BS_TOTAL + m] = v;
    }
}

// ===========================================================================
// Kernel 3: dt = softplus(dtlow @ w_dt + b)*0.099+0.001, output TRANSPOSED.
// ===========================================================================
__global__ __launch_bounds__(256) void dt_kernel(const float* __restrict__ Wdt,
                                                 const float* __restrict__ bdt) {
    __shared__ float As[64][64];
    __shared__ float Bs[64][68];
    const int tid = threadIdx.x;
    const int m0 = blockIdx.y * 64, d0 = blockIdx.x * 64;
    const int tx = tid & 15, ty = tid >> 4;
    float acc[4][4];
#pragma unroll
    for (int i = 0; i < 4; i++)
#pragma unroll
        for (int j = 0; j < 4; j++) acc[i][j] = 0.f;

    for (int i = tid; i < 1024; i += 256) {
        int r = i >> 4, c4 = (i & 15) * 4;
        *(float4*)&As[r][c4] = *(const float4*)(g_proj + (size_t)(m0 + r) * PDIM + c4);
        *(float4*)&Bs[r][c4] = *(const float4*)(Wdt + (size_t)r * DM + d0 + c4);
    }
    __syncthreads();
#pragma unroll 4
    for (int r = 0; r < 64; r++) {
        float ra[4], rb[4];
#pragma unroll
        for (int i = 0; i < 4; i++) ra[i] = As[ty * 4 + i][r];
        *(float4*)&rb[0] = *(const float4*)&Bs[r][tx * 4];
#pragma unroll
        for (int i = 0; i < 4; i++)
#pragma unroll
            for (int j = 0; j < 4; j++)
                acc[i][j] = fmaf(ra[i], rb[j], acc[i][j]);
    }
#pragma unroll
    for (int i = 0; i < 4; i++)
#pragma unroll
        for (int j = 0; j < 4; j++) {
            float z = acc[i][j] + bdt[d0 + tx * 4 + j];
            float sp = (z > 15.f) ? z : log1pf(__expf(z));
            acc[i][j] = sp * 0.099f + 0.001f;
        }
    __syncthreads();
    float* stg = &Bs[0][0];
#pragma unroll
    for (int j = 0; j < 4; j++)
        *(float4*)&stg[(tx * 4 + j) * 68 + ty * 4] =
            make_float4(acc[0][j], acc[1][j], acc[2][j], acc[3][j]);
    __syncthreads();
    {
        const int dl = tid >> 2, mc = (tid & 3) * 16;
        float* dst = g_dtT + (size_t)(d0 + dl) * BS_TOTAL + m0 + mc;
        const float* src = stg + dl * 68 + mc;
#pragma unroll
        for (int q = 0; q < 4; q++) *(float4*)(dst + q * 4) = *(const float4*)(src + q * 4);
    }
}

// ===========================================================================
// Kernel 4: G partials. Thread per 2m, 16 n. grid (16 mchunk, 16 ksplit).
// ===========================================================================
__global__ __launch_bounds__(128) void inp_part_kernel() {
    __shared__ float nAs[64 * NSTATE];
    const int tid = threadIdx.x;
    const int m0 = blockIdx.x * 256, k0 = blockIdx.y * 64;
    for (int i = tid; i < 64 * NSTATE; i += 128) nAs[i] = g_negA[k0 * NSTATE + i];
    __syncthreads();
    const int m = m0 + tid * 2;
    float acc[2][NSTATE];
#pragma unroll
    for (int i = 0; i < 2; i++)
#pragma unroll
        for (int n = 0; n < NSTATE; n++) acc[i][n] = 0.f;

#pragma unroll 2
    for (int kk = 0; kk < 64; kk++) {
        float2 dv = *(const float2*)(g_dtT + (size_t)(k0 + kk) * BS_TOTAL + m);
        float2 uv = *(const float2*)(g_xinT + (size_t)(k0 + kk) * BS_TOTAL + m);
        const float s0 = dv.x * uv.x, s1 = dv.y * uv.y;
#pragma unroll
        for (int n4 = 0; n4 < 4; n4++) {
            float4 a = *(const float4*)&nAs[kk * NSTATE + n4 * 4];
            acc[0][n4 * 4 + 0] = fmaf(s0, a.x, acc[0][n4 * 4 + 0]);
            acc[0][n4 * 4 + 1] = fmaf(s0, a.y, acc[0][n4 * 4 + 1]);
            acc[0][n4 * 4 + 2] = fmaf(s0, a.z, acc[0][n4 * 4 + 2]);
            acc[0][n4 * 4 + 3] = fmaf(s0, a.w, acc[0][n4 * 4 + 3]);
            acc[1][n4 * 4 + 0] = fmaf(s1, a.x, acc[1][n4 * 4 + 0]);
            acc[1][n4 * 4 + 1] = fmaf(s1, a.y, acc[1][n4 * 4 + 1]);
            acc[1][n4 * 4 + 2] = fmaf(s1, a.z, acc[1][n4 * 4 + 2]);
            acc[1][n4 * 4 + 3] = fmaf(s1, a.w, acc[1][n4 * 4 + 3]);
        }
    }
    float* o = g_inpP + ((size_t)blockIdx.y * BS_TOTAL + m) * NSTATE;
#pragma unroll
    for (int i = 0; i < 2; i++)
#pragma unroll
        for (int n4 = 0; n4 < 4; n4++)
            *(float4*)(o + i * NSTATE + n4 * 4) =
                make_float4(acc[i][n4 * 4], acc[i][n4 * 4 + 1],
                            acc[i][n4 * 4 + 2], acc[i][n4 * 4 + 3]);
}

__global__ __launch_bounds__(256) void inp_reduce_kernel() {
    const int idx = blockIdx.x * 256 + threadIdx.x;
    const int m = idx >> 4, n = idx & 15;
    float v = 0.f;
#pragma unroll
    for (int ks = 0; ks < 16; ks++)
        v += g_inpP[(size_t)ks * BS_TOTAL * NSTATE + idx];
    g_inpT[(size_t)n * BS_TOTAL + m] = v * g_BT[(size_t)n * BS_TOTAL + m];
}

// ===========================================================================
// Kernel 5: scan. Block = 8 groups of 16 lanes (128 thr), grid (128, 2).
// ===========================================================================
__global__ __launch_bounds__(128) void scan_kernel(const float* __restrict__ Dp,
                                                   float* __restrict__ out) {
    __shared__ float sy[2][8][8];
    const int tid = threadIdx.x;
    const int grp = tid >> 4, n = tid & 15;
    const int d0 = blockIdx.x * 8, b = blockIdx.y;
    const int d = d0 + grp;
    const float A1 = g_negA[d * NSTATE + n];
    const float Dpd = Dp[d];
    const size_t mb = (size_t)b * SEQ;
    const float* __restrict__ dtp = g_dtT + (size_t)d * BS_TOTAL + mb;
    const float* __restrict__ up = g_xinT + (size_t)d * BS_TOTAL + mb;
    const float* __restrict__ ip = g_inpT + (size_t)n * BS_TOTAL + mb;
    const float* __restrict__ cp = g_CT + (size_t)n * BS_TOTAL + mb;
    float* op = out + mb * DM + d0;

    float4 Da, Db, Ua, Ub, Ia, Ib, Ca, Cb;
    Da = *(const float4*)(dtp); Db = *(const float4*)(dtp + 4);
    Ua = *(const float4*)(up);  Ub = *(const float4*)(up + 4);
    Ia = *(const float4*)(ip);  Ib = *(const float4*)(ip + 4);
    Ca = *(const float4*)(cp);  Cb = *(const float4*)(cp + 4);

    float h = 0.f;
    for (int s0 = 0; s0 < SEQ; s0 += 8) {
        float4 nDa, nDb, nUa, nUb, nIa, nIb, nCa, nCb;
        if (s0 + 8 < SEQ) {
            nDa = *(const float4*)(dtp + s0 + 8); nDb = *(const float4*)(dtp + s0 + 12);
            nUa = *(const float4*)(up + s0 + 8);  nUb = *(const float4*)(up + s0 + 12);
            nIa = *(const float4*)(ip + s0 + 8);  nIb = *(const float4*)(ip + s0 + 12);
            nCa = *(const float4*)(cp + s0 + 8);  nCb = *(const float4*)(cp + s0 + 12);
        }
        float e[8], p[8];
        e[0] = __expf(Da.x * A1); e[1] = __expf(Da.y * A1);
        e[2] = __expf(Da.z * A1); e[3] = __expf(Da.w * A1);
        e[4] = __expf(Db.x * A1); e[5] = __expf(Db.y * A1);
        e[6] = __expf(Db.z * A1); e[7] = __expf(Db.w * A1);
        h = fmaf(e[0], h, Ia.x); p[0] = h * Ca.x;
        h = fmaf(e[1], h, Ia.y); p[1] = h * Ca.y;
        h = fmaf(e[2], h, Ia.z); p[2] = h * Ca.z;
        h = fmaf(e[3], h, Ia.w); p[3] = h * Ca.w;
        h = fmaf(e[4], h, Ib.x); p[4] = h * Cb.x;
        h = fmaf(e[5], h, Ib.y); p[5] = h * Cb.y;
        h = fmaf(e[6], h, Ib.z); p[6] = h * Cb.z;
        h = fmaf(e[7], h, Ib.w); p[7] = h * Cb.w;
#pragma unroll
        for (int j = 0; j < 8; j++) {
            p[j] += __shfl_xor_sync(0xffffffffu, p[j], 8);
            p[j] += __shfl_xor_sync(0xffffffffu, p[j], 4);
            p[j] += __shfl_xor_sync(0xffffffffu, p[j], 2);
            p[j] += __shfl_xor_sync(0xffffffffu, p[j], 1);
        }
        const int buf = (s0 >> 3) & 1;
        if (n == 0) {
            sy[buf][0][grp] = fmaf(Dpd, Ua.x, p[0]);
            sy[buf][1][grp] = fmaf(Dpd, Ua.y, p[1]);
            sy[buf][2][grp] = fmaf(Dpd, Ua.z, p[2]);
            sy[buf][3][grp] = fmaf(Dpd, Ua.w, p[3]);
            sy[buf][4][grp] = fmaf(Dpd, Ub.x, p[4]);
            sy[buf][5][grp] = fmaf(Dpd, Ub.y, p[5]);
            sy[buf][6][grp] = fmaf(Dpd, Ub.z, p[6]);
            sy[buf][7][grp] = fmaf(Dpd, Ub.w, p[7]);
        }
        __syncthreads();
        if (tid < 64) {
            const int j = tid >> 3, dd = tid & 7;
            op[(size_t)(s0 + j) * DM + dd] = sy[buf][j][dd];
        }
        Da = nDa; Db = nDb; Ua = nUa; Ub = nUb;
        Ia = nIa; Ib = nIb; Ca = nCa; Cb = nCb;
    }
}

// ===========================================================================
extern "C" void kernel_launch(void* const* d_in, const int* in_sizes, int n_in,
                              void* d_out, int out_size) {
    const float* x     = (const float*)d_in[0];
    const float* w_in  = (const float*)d_in[1];
    const float* w_x   = (const float*)d_in[2];
    const float* w_dt  = (const float*)d_in[3];
    const float* b_dt  = (const float*)d_in[4];
    const float* A_log = (const float*)d_in[5];
    const float* Dp    = (const float*)d_in[6];
    float* out = (float*)d_out;

    transpose_kernel<<<dim3(32, 32), dim3(32, 8)>>>(w_in);
    negA_kernel<<<64, 256>>>(A_log);
    gemm1_mma_kernel<<<dim3(DM / 128, BS_TOTAL / 128), 128>>>(x);
    proj_kernel<<<dim3(4, 12, 16), 256>>>(w_x);
    proj_reduce_kernel<<<(BS_TOTAL * PDIM) / 256, 256>>>();
    dt_kernel<<<dim3(DM / 64, BS_TOTAL / 64), 256>>>(w_dt, b_dt);
    inp_part_kernel<<<dim3(16, 16), 128>>>();
    inp_reduce_kernel<<<(BS_TOTAL * NSTATE) / 256, 256>>>();
    scan_kernel<<<dim3(128, 2), 128>>>(Dp, out);
}